// round 3
// baseline (speedup 1.0000x reference)
#include <cuda_runtime.h>
#include <cuda_bf16.h>
#include <cstdint>

#define NN   2048      // nodes
#define DD   256       // embedding size
#define CC   768       // cat size
#define VV   2         // variants
#define LL   16        // activities per variant
#define EMAX 32768     // 16*N edges
#define NCTA 128       // persistent grid size (must be <= #SMs for residency)

// ---------------- scratch (device globals; no allocation allowed) ----------------
__device__ float g_emb[2][VV][NN * DD];     // ping-pong per variant
__device__ float g_msg[VV][NN * DD];
__device__ float g_pi[VV][NN * CC];
__device__ float g_summary[VV][2][CC];      // parity ping-pong
__device__ float g_delta[VV][2][CC];
__device__ int   g_maskedList[VV][NN];
__device__ int   g_maskedCnt[VV][2];
__device__ int   g_act[VV][LL];
__device__ int   g_later[VV][LL][LL];
__device__ int   g_laterCnt[VV][LL];
__device__ int   g_has[VV][LL];
__device__ int   g_csrCnt[NN];
__device__ int   g_csrOff[NN + 1];
__device__ int   g_csrCur[NN];
__device__ int   g_csrSrc[EMAX];
__device__ unsigned g_barCount;
// W stacked [Wself;Wnbr] transposed: [N=256][K=512], bf16 hi/lo split
__device__ __nv_bfloat16 g_Wt_hi[DD * 2 * DD];
__device__ __nv_bfloat16 g_Wt_lo[DD * 2 * DD];

// ---------------- grid barrier (all NCTA CTAs resident) ----------------
__device__ __forceinline__ unsigned ld_acq(unsigned* p) {
    unsigned v;
    asm volatile("ld.acquire.gpu.u32 %0, [%1];" : "=r"(v) : "l"(p) : "memory");
    return v;
}
__device__ __forceinline__ void grid_sync(unsigned target) {
    __syncthreads();
    if (threadIdx.x == 0) {
        __threadfence();                       // release
        atomicAdd(&g_barCount, 1u);
        while (ld_acq(&g_barCount) < target) {}
    }
    __syncthreads();
}

// ---------------- init: copy embeddings, zero pi / csr counts / barrier ----------------
__global__ void init_k(const float* __restrict__ embeddings) {
    int t0 = blockIdx.x * blockDim.x + threadIdx.x;
    int stride = gridDim.x * blockDim.x;
    if (t0 == 0) g_barCount = 0;
    for (int idx = t0; idx < NN * DD; idx += stride) {
        float e = embeddings[idx];
        g_emb[0][0][idx] = e;
        g_emb[0][1][idx] = e;
    }
    for (int idx = t0; idx < VV * NN * CC; idx += stride) {
        ((float*)g_pi)[idx] = 0.0f;
    }
    for (int idx = t0; idx < NN; idx += stride) g_csrCnt[idx] = 0;
}

// ---------------- W convert+transpose (once): bf16 hi/lo ----------------
__global__ void wconv_k(const float* __restrict__ Wself, const float* __restrict__ Wnbr) {
    int t0 = blockIdx.x * blockDim.x + threadIdx.x;
    int stride = gridDim.x * blockDim.x;
    for (int idx = t0; idx < DD * 2 * DD; idx += stride) {
        int n = idx >> 9;           // 0..255
        int k = idx & 511;          // 0..511
        float w = (k < DD) ? Wself[k * DD + n] : Wnbr[(k - DD) * DD + n];
        __nv_bfloat16 hi = __float2bfloat16(w);
        __nv_bfloat16 lo = __float2bfloat16(w - __bfloat162float(hi));
        g_Wt_hi[n * 512 + k] = hi;
        g_Wt_lo[n * 512 + k] = lo;
    }
}

// ---------------- prep: per-(v,i) activity, distinct later-set, has flag ----------------
__global__ void prep_k(const int* __restrict__ variants, const int* __restrict__ adj) {
    int t = threadIdx.x;                 // 1024 threads
    int w = t >> 5, lane = t & 31;
    if (w < VV * LL) {
        int v = w >> 4, i = w & 15;
        int a = variants[v * LL + i];
        if (lane == 0) {
            g_act[v][i] = a;
            int cnt = 0;
            for (int j = i + 1; j < LL; j++) {
                int nd = variants[v * LL + j];
                bool dup = false;
                for (int q = 0; q < cnt; q++) if (g_later[v][i][q] == nd) dup = true;
                if (!dup) g_later[v][i][cnt++] = nd;
            }
            g_laterCnt[v][i] = cnt;
        }
        int any = 0;
        for (int p = lane; p < NN; p += 32) any |= (adj[(size_t)a * NN + p] != 0);
        any = __any_sync(0xffffffffu, any);
        if (lane == 0) g_has[v][i] = any;
    }
    // zero summary / delta / masked counters (both parities)
    for (int idx = t; idx < VV * 2 * CC; idx += blockDim.x) {
        ((float*)g_summary)[idx] = 0.0f;
        ((float*)g_delta)[idx] = 0.0f;
    }
    if (t < VV * 2) ((int*)g_maskedCnt)[t] = 0;
}

// ---------------- CSR build (dst-major) ----------------
__global__ void csr_count_k(const int* __restrict__ ei, int E) {
    int t0 = blockIdx.x * blockDim.x + threadIdx.x;
    int stride = gridDim.x * blockDim.x;
    for (int e = t0; e < E; e += stride) atomicAdd(&g_csrCnt[ei[E + e]], 1);
}

__global__ void csr_scan_k() {
    __shared__ int s[2][NN];
    int t = threadIdx.x;                 // 1024 threads
    s[0][t] = g_csrCnt[t];
    s[0][t + 1024] = g_csrCnt[t + 1024];
    __syncthreads();
    int src = 0;
    for (int off = 1; off < NN; off <<= 1) {
        int dstb = src ^ 1;
        for (int idx = t; idx < NN; idx += 1024) {
            int val = s[src][idx];
            if (idx >= off) val += s[src][idx - off];
            s[dstb][idx] = val;
        }
        __syncthreads();
        src = dstb;
    }
    for (int idx = t; idx < NN; idx += 1024) {
        int excl = (idx == 0) ? 0 : s[src][idx - 1];
        g_csrOff[idx] = excl;
        g_csrCur[idx] = excl;
    }
    if (t == 0) g_csrOff[NN] = s[src][NN - 1];
}

__global__ void csr_fill_k(const int* __restrict__ ei, int E) {
    int t0 = blockIdx.x * blockDim.x + threadIdx.x;
    int stride = gridDim.x * blockDim.x;
    for (int e = t0; e < E; e += stride) {
        int dst = ei[E + e];
        int pos = atomicAdd(&g_csrCur[dst], 1);
        g_csrSrc[pos] = ei[e];
    }
}

// ---------------- GEMM helpers ----------------
#define SA 40
#define SB 40

__device__ __forceinline__ void mma16816(float* c, const uint32_t* a, const uint32_t* b) {
    asm volatile(
        "mma.sync.aligned.m16n8k16.row.col.f32.bf16.bf16.f32 "
        "{%0,%1,%2,%3}, {%4,%5,%6,%7}, {%8,%9}, {%0,%1,%2,%3};"
        : "+f"(c[0]), "+f"(c[1]), "+f"(c[2]), "+f"(c[3])
        : "r"(a[0]), "r"(a[1]), "r"(a[2]), "r"(a[3]), "r"(b[0]), "r"(b[1]));
}

// ---------------- fused persistent loop kernel ----------------
__global__ __launch_bounds__(256) void fused_loop_k(
    const int* __restrict__ adj, const float* __restrict__ bias, float* __restrict__ out)
{
    __shared__ __align__(16) __nv_bfloat16 As[2][128][SA];   // [hi/lo]
    __shared__ __align__(16) __nv_bfloat16 Bs[2][64][SB];

    const int bx = blockIdx.x;
    const int t  = threadIdx.x;
    const int lane = t & 31;
    const int warp = t >> 5;

    unsigned target = 0;
    int cur = 0;

    for (int i = 0; i < LL; i++) {
        const int par = i & 1;

        // ================= P1: stepA + msg =================
        // ---- stepA: scan (v,p) pairs ----
        for (int v = 0; v < VV; v++) {
            if (!g_has[v][i]) continue;
            const int a = g_act[v][i];
            const int cnt = g_laterCnt[v][i];
            const float* emb = g_emb[cur][v];
            for (int p = bx; p < NN; p += NCTA) {
                if (adj[(size_t)a * NN + p] == 0) continue;   // uniform

                float4 catv = make_float4(0.f, 0.f, 0.f, 0.f);
                if (t < 64)        catv = *(const float4*)&emb[(size_t)p * DD + t * 4];
                else if (t < 128)  catv = *(const float4*)&emb[(size_t)a * DD + (t - 64) * 4];

                int dest = 0;
                for (int q = 0; q < cnt; q++) {
                    int lk = g_later[v][i][q];
                    if (adj[(size_t)p * NN + lk] != 0) {
                        dest = 1;
                        if (t >= 128 && t < 192) {
                            const float4 s = *(const float4*)&emb[(size_t)lk * DD + (t - 128) * 4];
                            catv.x += s.x; catv.y += s.y; catv.z += s.z; catv.w += s.w;
                        }
                    }
                }
                if (!dest) continue;                           // uniform

                if (t < 192) {
                    float* pir = &g_pi[v][(size_t)p * CC];
                    float4 old = *(float4*)&pir[t * 4];
                    float4 nw = make_float4(old.x + catv.x, old.y + catv.y,
                                            old.z + catv.z, old.w + catv.w);
                    *(float4*)&pir[t * 4] = nw;
                    float* del = g_delta[v][par];
                    atomicAdd(&del[t * 4 + 0], nw.x);
                    atomicAdd(&del[t * 4 + 1], nw.y);
                    atomicAdd(&del[t * 4 + 2], nw.z);
                    atomicAdd(&del[t * 4 + 3], nw.w);
                }
                if (t == 0) {
                    int idx = atomicAdd(&g_maskedCnt[v][par], 1);
                    if (idx < NN) g_maskedList[v][idx] = p;
                }
            }
        }
        // ---- msg: segment sum over CSR; 4 rows at a time, 64 threads/row ----
        {
            const int sub = t >> 6;        // 0..3
            const int ln  = t & 63;        // column group
            const int base = bx * 32;
            for (int jj = sub; jj < 32; jj += 4) {
                int job = base + jj;                   // 0..4095
                int v = job >> 11;
                int dst = job & 2047;
                if (!g_has[v][i]) continue;
                const float4* emb4 = (const float4*)g_emb[cur][v];
                float4 acc = make_float4(0.f, 0.f, 0.f, 0.f);
                int s0 = g_csrOff[dst], s1 = g_csrOff[dst + 1];
#pragma unroll 4
                for (int j = s0; j < s1; j++) {
                    int s = g_csrSrc[j];
                    float4 e = emb4[(size_t)s * (DD / 4) + ln];
                    acc.x += e.x; acc.y += e.y; acc.z += e.z; acc.w += e.w;
                }
                ((float4*)g_msg[v])[(size_t)dst * (DD / 4) + ln] = acc;
            }
        }
        target += NCTA;
        grid_sync(target);

        // ================= P2: stepBC + GEMM =================
        // ---- bookkeeping: blocks 0/1 advance summary/delta parity for v=bx ----
        if (bx < VV) {
            int v = bx;
            if (t < 192) {
                float4 s = *(float4*)&g_summary[v][par][t * 4];
                float4 d = *(float4*)&g_delta[v][par][t * 4];
                s.x += d.x; s.y += d.y; s.z += d.z; s.w += d.w;
                *(float4*)&g_summary[v][par ^ 1][t * 4] = s;
                *(float4*)&g_delta[v][par ^ 1][t * 4] = make_float4(0.f, 0.f, 0.f, 0.f);
            }
            if (t == 0) g_maskedCnt[v][par ^ 1] = 0;
        }
        // ---- stepBC: pi[masked] += (summary_old + delta) ----
        for (int v = 0; v < VV; v++) {
            if (!g_has[v][i]) continue;
            int cnt = g_maskedCnt[v][par];
            if (cnt > NN) cnt = NN;
            if (cnt == 0) continue;
            float4 sd = make_float4(0.f, 0.f, 0.f, 0.f);
            if (t < 192) {
                float4 s = *(float4*)&g_summary[v][par][t * 4];
                float4 d = *(float4*)&g_delta[v][par][t * 4];
                sd = make_float4(s.x + d.x, s.y + d.y, s.z + d.z, s.w + d.w);
            }
            for (int m = bx; m < cnt; m += NCTA) {
                int p = g_maskedList[v][m];
                if (t < 192) {
                    float* pir = &g_pi[v][(size_t)p * CC];
                    float4 o = *(float4*)&pir[t * 4];
                    o.x += sd.x; o.y += sd.y; o.z += sd.z; o.w += sd.w;
                    *(float4*)&pir[t * 4] = o;
                }
            }
        }

        // ---- GEMM tile: bx -> (m-tile, n-tile) = (bx>>2, bx&3) ----
        {
            const int m0g = (bx >> 2) * 128;     // global row 0..3968
            const int v = m0g >> 11;
            const int m0 = m0g & 2047;
            const int n0 = (bx & 3) * 64;
            const float* X = g_emb[cur][v];
            float* O = g_emb[cur ^ 1][v];

            if (!g_has[v][i]) {
                // encoder skipped: emb passes through
                int r = t >> 1, ch = (t & 1) * 32;
#pragma unroll
                for (int j = 0; j < 8; j++) {
                    *(float4*)&O[(size_t)(m0 + r) * DD + n0 + ch + j * 4] =
                        *(const float4*)&X[(size_t)(m0 + r) * DD + n0 + ch + j * 4];
                }
            } else {
                const float* Msg = g_msg[v];
                const int wm = warp >> 1;
                const int wn = warp & 1;
                const int g8 = lane >> 2;
                const int tq = lane & 3;

                float acc[2][4][4];
#pragma unroll
                for (int mt = 0; mt < 2; mt++)
#pragma unroll
                    for (int nt = 0; nt < 4; nt++)
#pragma unroll
                        for (int e = 0; e < 4; e++) acc[mt][nt][e] = 0.f;

                const int aq = t & 7;
                const int ar0 = t >> 3;
                const int bn = t >> 2;
                const int bseg = t & 3;

                for (int kt = 0; kt < 512; kt += 32) {
                    const float* Asrc = (kt < 256) ? X : Msg;
                    int colbase = (kt & 255) + aq * 4;
#pragma unroll
                    for (int rr = 0; rr < 4; rr++) {
                        int row = ar0 + rr * 32;
                        float4 f = *(const float4*)&Asrc[(size_t)(m0 + row) * DD + colbase];
                        __nv_bfloat162 h0 = __floats2bfloat162_rn(f.x, f.y);
                        __nv_bfloat162 h1 = __floats2bfloat162_rn(f.z, f.w);
                        __nv_bfloat162 l0 = __floats2bfloat162_rn(f.x - __bfloat162float(h0.x),
                                                                  f.y - __bfloat162float(h0.y));
                        __nv_bfloat162 l1 = __floats2bfloat162_rn(f.z - __bfloat162float(h1.x),
                                                                  f.w - __bfloat162float(h1.y));
                        *(__nv_bfloat162*)&As[0][row][aq * 4]     = h0;
                        *(__nv_bfloat162*)&As[0][row][aq * 4 + 2] = h1;
                        *(__nv_bfloat162*)&As[1][row][aq * 4]     = l0;
                        *(__nv_bfloat162*)&As[1][row][aq * 4 + 2] = l1;
                    }
                    {
                        size_t woff = (size_t)(n0 + bn) * 512 + kt + bseg * 8;
                        *(uint4*)&Bs[0][bn][bseg * 8] = *(const uint4*)&g_Wt_hi[woff];
                        *(uint4*)&Bs[1][bn][bseg * 8] = *(const uint4*)&g_Wt_lo[woff];
                    }
                    __syncthreads();

#pragma unroll
                    for (int sub = 0; sub < 2; sub++) {
                        int kb = sub * 16;
                        uint32_t ah[2][4], al[2][4], bh[4][2], bl[4][2];
#pragma unroll
                        for (int mt = 0; mt < 2; mt++) {
                            int r = wm * 32 + mt * 16 + g8;
                            ah[mt][0] = *(const uint32_t*)&As[0][r][kb + tq * 2];
                            ah[mt][1] = *(const uint32_t*)&As[0][r + 8][kb + tq * 2];
                            ah[mt][2] = *(const uint32_t*)&As[0][r][kb + tq * 2 + 8];
                            ah[mt][3] = *(const uint32_t*)&As[0][r + 8][kb + tq * 2 + 8];
                            al[mt][0] = *(const uint32_t*)&As[1][r][kb + tq * 2];
                            al[mt][1] = *(const uint32_t*)&As[1][r + 8][kb + tq * 2];
                            al[mt][2] = *(const uint32_t*)&As[1][r][kb + tq * 2 + 8];
                            al[mt][3] = *(const uint32_t*)&As[1][r + 8][kb + tq * 2 + 8];
                        }
#pragma unroll
                        for (int nt = 0; nt < 4; nt++) {
                            int n = wn * 32 + nt * 8 + g8;
                            bh[nt][0] = *(const uint32_t*)&Bs[0][n][kb + tq * 2];
                            bh[nt][1] = *(const uint32_t*)&Bs[0][n][kb + tq * 2 + 8];
                            bl[nt][0] = *(const uint32_t*)&Bs[1][n][kb + tq * 2];
                            bl[nt][1] = *(const uint32_t*)&Bs[1][n][kb + tq * 2 + 8];
                        }
#pragma unroll
                        for (int mt = 0; mt < 2; mt++)
#pragma unroll
                            for (int nt = 0; nt < 4; nt++) {
                                mma16816(acc[mt][nt], ah[mt], bh[nt]);
                                mma16816(acc[mt][nt], ah[mt], bl[nt]);
                                mma16816(acc[mt][nt], al[mt], bh[nt]);
                            }
                    }
                    __syncthreads();
                }

                // epilogue: + bias, relu, store fp32
#pragma unroll
                for (int mt = 0; mt < 2; mt++) {
                    int row = m0 + wm * 32 + mt * 16 + g8;
#pragma unroll
                    for (int nt = 0; nt < 4; nt++) {
                        int col = n0 + wn * 32 + nt * 8 + tq * 2;
                        float b0 = bias[col], b1 = bias[col + 1];
                        float2 o0, o1;
                        o0.x = fmaxf(acc[mt][nt][0] + b0, 0.f);
                        o0.y = fmaxf(acc[mt][nt][1] + b1, 0.f);
                        o1.x = fmaxf(acc[mt][nt][2] + b0, 0.f);
                        o1.y = fmaxf(acc[mt][nt][3] + b1, 0.f);
                        *(float2*)&O[(size_t)row * DD + col] = o0;
                        *(float2*)&O[(size_t)(row + 8) * DD + col] = o1;
                    }
                }
            }
        }
        target += NCTA;
        grid_sync(target);
        cur ^= 1;
    }

    // ---------------- final: out = pi[0] + pi[1] ----------------
    {
        const float4* p0 = (const float4*)g_pi[0];
        const float4* p1 = (const float4*)g_pi[1];
        float4* o4 = (float4*)out;
        int total = NN * CC / 4;
        for (int idx = bx * 256 + t; idx < total; idx += NCTA * 256) {
            float4 a = p0[idx], b = p1[idx];
            o4[idx] = make_float4(a.x + b.x, a.y + b.y, a.z + b.z, a.w + b.w);
        }
    }
}

// ---------------- launch ----------------
extern "C" void kernel_launch(void* const* d_in, const int* in_sizes, int n_in,
                              void* d_out, int out_size) {
    const float* embeddings = (const float*)d_in[0];
    const float* Wself      = (const float*)d_in[1];
    const float* Wnbr       = (const float*)d_in[2];
    const float* bvec       = (const float*)d_in[3];
    const int*   variants   = (const int*)d_in[4];
    const int*   original   = (const int*)d_in[5];
    const int*   edge_index = (const int*)d_in[6];
    float* out = (float*)d_out;
    int E = in_sizes[6] / 2;

    init_k<<<512, 256>>>(embeddings);
    wconv_k<<<256, 256>>>(Wself, Wnbr);
    prep_k<<<1, 1024>>>(variants, original);
    csr_count_k<<<128, 256>>>(edge_index, E);
    csr_scan_k<<<1, 1024>>>();
    csr_fill_k<<<128, 256>>>(edge_index, E);

    fused_loop_k<<<NCTA, 256>>>(original, bvec, out);
}

// round 4
// speedup vs baseline: 1.4652x; 1.4652x over previous
#include <cuda_runtime.h>
#include <cuda_bf16.h>
#include <cstdint>

#define NN   2048      // nodes
#define DD   256       // embedding size
#define CC   768       // cat size
#define VV   2         // variants
#define LL   16        // activities per variant
#define EMAX 32768     // 16*N edges

// ---------------- scratch (device globals; no allocation allowed) ----------------
__device__ float g_emb[2][VV][NN * DD];     // ping-pong per variant
__device__ float g_msg[VV][NN * DD];
__device__ float g_pi[VV][NN * CC];
__device__ float g_summary[VV][2][CC];      // parity ping-pong
__device__ float g_delta[VV][2][CC];
__device__ int   g_maskedList[VV][NN];
__device__ int   g_maskedCnt[VV][2];
__device__ int   g_act[VV][LL];
__device__ int   g_later[VV][LL][LL];
__device__ int   g_laterCnt[VV][LL];
__device__ int   g_has[VV][LL];
__device__ int   g_csrCnt[NN];
__device__ int   g_csrOff[NN + 1];
__device__ int   g_csrCur[NN];
__device__ int   g_csrSrc[EMAX];
// W stacked [Wself;Wnbr] transposed: [N=256][K=512], bf16 hi/lo split
__device__ __nv_bfloat16 g_Wt_hi[DD * 2 * DD];
__device__ __nv_bfloat16 g_Wt_lo[DD * 2 * DD];

// ---------------- S1: init emb/pi/csrCnt + W convert ----------------
__global__ void s1_init_k(const float* __restrict__ embeddings,
                          const float* __restrict__ Wself, const float* __restrict__ Wnbr) {
    int t0 = blockIdx.x * blockDim.x + threadIdx.x;
    int stride = gridDim.x * blockDim.x;
    for (int idx = t0; idx < NN * DD; idx += stride) {
        float e = embeddings[idx];
        g_emb[0][0][idx] = e;
        g_emb[0][1][idx] = e;
    }
    for (int idx = t0; idx < VV * NN * CC; idx += stride) {
        ((float*)g_pi)[idx] = 0.0f;
    }
    for (int idx = t0; idx < NN; idx += stride) g_csrCnt[idx] = 0;
    for (int idx = t0; idx < DD * 2 * DD; idx += stride) {
        int n = idx >> 9;           // 0..255
        int k = idx & 511;          // 0..511
        float w = (k < DD) ? Wself[k * DD + n] : Wnbr[(k - DD) * DD + n];
        __nv_bfloat16 hi = __float2bfloat16(w);
        __nv_bfloat16 lo = __float2bfloat16(w - __bfloat162float(hi));
        g_Wt_hi[n * 512 + k] = hi;
        g_Wt_lo[n * 512 + k] = lo;
    }
}

// ---------------- S2: csr_count (blocks 0..127) + prep (block 128) ----------------
__global__ void s2_prep_count_k(const int* __restrict__ variants, const int* __restrict__ adj,
                                const int* __restrict__ ei, int E) {
    int t = threadIdx.x;                 // 256 threads
    if (blockIdx.x < 128) {
        int t0 = blockIdx.x * 256 + t;
        for (int e = t0; e < E; e += 128 * 256) atomicAdd(&g_csrCnt[ei[E + e]], 1);
        return;
    }
    // prep block
    int warp = t >> 5, lane = t & 31;
    for (int pr = warp; pr < VV * LL; pr += 8) {
        int v = pr >> 4, i = pr & 15;
        int a = variants[v * LL + i];
        if (lane == 0) {
            g_act[v][i] = a;
            int cnt = 0;
            for (int j = i + 1; j < LL; j++) {
                int nd = variants[v * LL + j];
                bool dup = false;
                for (int q = 0; q < cnt; q++) if (g_later[v][i][q] == nd) dup = true;
                if (!dup) g_later[v][i][cnt++] = nd;
            }
            g_laterCnt[v][i] = cnt;
        }
        int any = 0;
        for (int p = lane; p < NN; p += 32) any |= (adj[(size_t)a * NN + p] != 0);
        any = __any_sync(0xffffffffu, any);
        if (lane == 0) g_has[v][i] = any;
    }
    for (int idx = t; idx < VV * 2 * CC; idx += 256) {
        ((float*)g_summary)[idx] = 0.0f;
        ((float*)g_delta)[idx] = 0.0f;
    }
    if (t < VV * 2) ((int*)g_maskedCnt)[t] = 0;
}

// ---------------- S3: csr scan + fill (single block) ----------------
__global__ void s3_scan_fill_k(const int* __restrict__ ei, int E) {
    __shared__ int s[2][NN];
    int t = threadIdx.x;                 // 1024 threads
    s[0][t] = g_csrCnt[t];
    s[0][t + 1024] = g_csrCnt[t + 1024];
    __syncthreads();
    int src = 0;
    for (int off = 1; off < NN; off <<= 1) {
        int dstb = src ^ 1;
        for (int idx = t; idx < NN; idx += 1024) {
            int val = s[src][idx];
            if (idx >= off) val += s[src][idx - off];
            s[dstb][idx] = val;
        }
        __syncthreads();
        src = dstb;
    }
    for (int idx = t; idx < NN; idx += 1024) {
        int excl = (idx == 0) ? 0 : s[src][idx - 1];
        g_csrOff[idx] = excl;
        g_csrCur[idx] = excl;
    }
    if (t == 0) g_csrOff[NN] = s[src][NN - 1];
    __syncthreads();
    for (int e = t; e < E; e += 1024) {
        int dst = ei[E + e];
        int pos = atomicAdd(&g_csrCur[dst], 1);
        g_csrSrc[pos] = ei[e];
    }
}

// ---------------- P1: stepA + msg, block = (p, v), 192 threads ----------------
__global__ __launch_bounds__(192) void p1_k(const int* __restrict__ adj, int i, int cur, int par) {
    const int p = blockIdx.x, v = blockIdx.y;
    const int t = threadIdx.x;
    __shared__ float4 sp[2][64];

    if (!g_has[v][i]) return;
    const float* emb = g_emb[cur][v];

    // ---- stepA for (p, v) ----
    const int a = g_act[v][i];
    if (adj[(size_t)a * NN + p] != 0) {
        const int cnt = g_laterCnt[v][i];
        float4 catv = make_float4(0.f, 0.f, 0.f, 0.f);
        if (t < 64)        catv = *(const float4*)&emb[(size_t)p * DD + t * 4];
        else if (t < 128)  catv = *(const float4*)&emb[(size_t)a * DD + (t - 64) * 4];

        int dest = 0;
        for (int q = 0; q < cnt; q++) {
            int lk = g_later[v][i][q];
            if (adj[(size_t)p * NN + lk] != 0) {
                dest = 1;
                if (t >= 128) {
                    const float4 s = *(const float4*)&emb[(size_t)lk * DD + (t - 128) * 4];
                    catv.x += s.x; catv.y += s.y; catv.z += s.z; catv.w += s.w;
                }
            }
        }
        if (dest) {
            float* pir = &g_pi[v][(size_t)p * CC];
            float4 old = *(float4*)&pir[t * 4];
            float4 nw = make_float4(old.x + catv.x, old.y + catv.y,
                                    old.z + catv.z, old.w + catv.w);
            *(float4*)&pir[t * 4] = nw;
            float* del = g_delta[v][par];
            atomicAdd(&del[t * 4 + 0], nw.x);
            atomicAdd(&del[t * 4 + 1], nw.y);
            atomicAdd(&del[t * 4 + 2], nw.z);
            atomicAdd(&del[t * 4 + 3], nw.w);
            if (t == 0) {
                int idx = atomicAdd(&g_maskedCnt[v][par], 1);
                if (idx < NN) g_maskedList[v][idx] = p;
            }
        }
    }

    // ---- msg for dst = p: 3-way edge split, smem reduce ----
    {
        const float4* emb4 = (const float4*)emb;
        const int g = t >> 6;         // 0..2
        const int ln = t & 63;        // col group
        float4 acc = make_float4(0.f, 0.f, 0.f, 0.f);
        const int s0 = g_csrOff[p], s1 = g_csrOff[p + 1];
        for (int j = s0 + g; j < s1; j += 3) {
            int s = g_csrSrc[j];
            float4 e = emb4[(size_t)s * (DD / 4) + ln];
            acc.x += e.x; acc.y += e.y; acc.z += e.z; acc.w += e.w;
        }
        if (g > 0) sp[g - 1][ln] = acc;
        __syncthreads();
        if (g == 0) {
            float4 p1v = sp[0][ln], p2v = sp[1][ln];
            acc.x += p1v.x + p2v.x; acc.y += p1v.y + p2v.y;
            acc.z += p1v.z + p2v.z; acc.w += p1v.w + p2v.w;
            ((float4*)g_msg[v])[(size_t)p * (DD / 4) + ln] = acc;
        }
    }
}

// ---------------- GEMM helpers ----------------
#define SA 40
#define SB 40

__device__ __forceinline__ void mma16816(float* c, const uint32_t* a, const uint32_t* b) {
    asm volatile(
        "mma.sync.aligned.m16n8k16.row.col.f32.bf16.bf16.f32 "
        "{%0,%1,%2,%3}, {%4,%5,%6,%7}, {%8,%9}, {%0,%1,%2,%3};"
        : "+f"(c[0]), "+f"(c[1]), "+f"(c[2]), "+f"(c[3])
        : "r"(a[0]), "r"(a[1]), "r"(a[2]), "r"(a[3]), "r"(b[0]), "r"(b[1]));
}
__device__ __forceinline__ void ldsm4(uint32_t* r, uint32_t addr) {
    asm volatile("ldmatrix.sync.aligned.m8n8.x4.shared.b16 {%0,%1,%2,%3}, [%4];"
        : "=r"(r[0]), "=r"(r[1]), "=r"(r[2]), "=r"(r[3]) : "r"(addr));
}

// ---------------- P2: stepBC + GEMM, 128 blocks x 256 threads ----------------
__global__ __launch_bounds__(256) void p2_k(const float* __restrict__ bias, int i, int cur, int par) {
    const int bx = blockIdx.x;
    const int t = threadIdx.x;
    const int lane = t & 31;
    const int warp = t >> 5;

    // ---- bookkeeping: blocks 0/1 advance parity state for v=bx ----
    if (bx < VV) {
        int v = bx;
        if (t < 192) {
            float4 s = *(float4*)&g_summary[v][par][t * 4];
            float4 d = *(float4*)&g_delta[v][par][t * 4];
            s.x += d.x; s.y += d.y; s.z += d.z; s.w += d.w;
            *(float4*)&g_summary[v][par ^ 1][t * 4] = s;
            *(float4*)&g_delta[v][par ^ 1][t * 4] = make_float4(0.f, 0.f, 0.f, 0.f);
        }
        if (t == 0) g_maskedCnt[v][par ^ 1] = 0;
    }
    // ---- stepBC: pi[masked] += (summary_old + delta) ----
    for (int v = 0; v < VV; v++) {
        if (!g_has[v][i]) continue;
        int cnt = g_maskedCnt[v][par];
        if (cnt > NN) cnt = NN;
        if (cnt == 0) continue;
        float4 sd = make_float4(0.f, 0.f, 0.f, 0.f);
        if (t < 192) {
            float4 s = *(float4*)&g_summary[v][par][t * 4];
            float4 d = *(float4*)&g_delta[v][par][t * 4];
            sd = make_float4(s.x + d.x, s.y + d.y, s.z + d.z, s.w + d.w);
        }
        for (int m = bx; m < cnt; m += 128) {
            int p = g_maskedList[v][m];
            if (t < 192) {
                float* pir = &g_pi[v][(size_t)p * CC];
                float4 o = *(float4*)&pir[t * 4];
                o.x += sd.x; o.y += sd.y; o.z += sd.z; o.w += sd.w;
                *(float4*)&pir[t * 4] = o;
            }
        }
    }

    // ---- GEMM tile: bx -> (m-tile, n-tile) = (bx>>2, bx&3) ----
    const int m0g = (bx >> 2) * 128;
    const int v = m0g >> 11;
    const int m0 = m0g & 2047;
    const int n0 = (bx & 3) * 64;
    const float* X = g_emb[cur][v];
    float* O = g_emb[cur ^ 1][v];

    if (!g_has[v][i]) {
        int r = t >> 1, ch = (t & 1) * 32;
#pragma unroll
        for (int j = 0; j < 8; j++) {
            *(float4*)&O[(size_t)(m0 + r) * DD + n0 + ch + j * 4] =
                *(const float4*)&X[(size_t)(m0 + r) * DD + n0 + ch + j * 4];
        }
        return;
    }

    const float* Msg = g_msg[v];
    __shared__ __align__(16) __nv_bfloat16 As[2][128][SA];   // [hi/lo]
    __shared__ __align__(16) __nv_bfloat16 Bs[2][64][SB];

    const int wm = warp >> 1;            // 0..3
    const int wn = warp & 1;             // 0..1
    const int g8 = lane >> 2;
    const int tq = lane & 3;

    float acc[2][4][4];
#pragma unroll
    for (int mt = 0; mt < 2; mt++)
#pragma unroll
        for (int nt = 0; nt < 4; nt++)
#pragma unroll
            for (int e = 0; e < 4; e++) acc[mt][nt][e] = 0.f;

    // precompute ldmatrix lane addresses (tile smem reused every kt)
    uint32_t aaddr[2][2], baddr[2][2];   // [mt|q][h]
    {
        int arow = wm * 32 + (lane & 15);
        int acol = (lane >> 4) * 8;
        aaddr[0][0] = (uint32_t)__cvta_generic_to_shared(&As[0][arow][acol]);
        aaddr[1][0] = (uint32_t)__cvta_generic_to_shared(&As[0][arow + 16][acol]);
        aaddr[0][1] = (uint32_t)__cvta_generic_to_shared(&As[1][arow][acol]);
        aaddr[1][1] = (uint32_t)__cvta_generic_to_shared(&As[1][arow + 16][acol]);
        int brow = wn * 32 + (lane & 7) + ((lane >> 4) << 3);
        int bcol = ((lane >> 3) & 1) * 8;
        baddr[0][0] = (uint32_t)__cvta_generic_to_shared(&Bs[0][brow][bcol]);
        baddr[1][0] = (uint32_t)__cvta_generic_to_shared(&Bs[0][brow + 16][bcol]);
        baddr[0][1] = (uint32_t)__cvta_generic_to_shared(&Bs[1][brow][bcol]);
        baddr[1][1] = (uint32_t)__cvta_generic_to_shared(&Bs[1][brow + 16][bcol]);
    }

    const int aq = t & 7;
    const int ar0 = t >> 3;
    const int bn = t >> 2;
    const int bseg = t & 3;

    for (int kt = 0; kt < 512; kt += 32) {
        const float* Asrc = (kt < 256) ? X : Msg;
        int colbase = (kt & 255) + aq * 4;
#pragma unroll
        for (int rr = 0; rr < 4; rr++) {
            int row = ar0 + rr * 32;
            float4 f = *(const float4*)&Asrc[(size_t)(m0 + row) * DD + colbase];
            __nv_bfloat162 h0 = __floats2bfloat162_rn(f.x, f.y);
            __nv_bfloat162 h1 = __floats2bfloat162_rn(f.z, f.w);
            __nv_bfloat162 l0 = __floats2bfloat162_rn(f.x - __bfloat162float(h0.x),
                                                      f.y - __bfloat162float(h0.y));
            __nv_bfloat162 l1 = __floats2bfloat162_rn(f.z - __bfloat162float(h1.x),
                                                      f.w - __bfloat162float(h1.y));
            *(__nv_bfloat162*)&As[0][row][aq * 4]     = h0;
            *(__nv_bfloat162*)&As[0][row][aq * 4 + 2] = h1;
            *(__nv_bfloat162*)&As[1][row][aq * 4]     = l0;
            *(__nv_bfloat162*)&As[1][row][aq * 4 + 2] = l1;
        }
        {
            size_t woff = (size_t)(n0 + bn) * 512 + kt + bseg * 8;
            *(uint4*)&Bs[0][bn][bseg * 8] = *(const uint4*)&g_Wt_hi[woff];
            *(uint4*)&Bs[1][bn][bseg * 8] = *(const uint4*)&g_Wt_lo[woff];
        }
        __syncthreads();

#pragma unroll
        for (int sub = 0; sub < 2; sub++) {
            uint32_t off = sub * 32;     // 16 bf16 = 32 bytes
            uint32_t ah0[4], ah1[4], al0[4], al1[4];
            uint32_t bh0[4], bh1[4], bl0[4], bl1[4];
            ldsm4(ah0, aaddr[0][0] + off);
            ldsm4(ah1, aaddr[1][0] + off);
            ldsm4(al0, aaddr[0][1] + off);
            ldsm4(al1, aaddr[1][1] + off);
            ldsm4(bh0, baddr[0][0] + off);
            ldsm4(bh1, baddr[1][0] + off);
            ldsm4(bl0, baddr[0][1] + off);
            ldsm4(bl1, baddr[1][1] + off);
#pragma unroll
            for (int mt = 0; mt < 2; mt++) {
                const uint32_t* ah = mt ? ah1 : ah0;
                const uint32_t* al = mt ? al1 : al0;
                mma16816(acc[mt][0], ah, bh0 + 0);
                mma16816(acc[mt][0], ah, bl0 + 0);
                mma16816(acc[mt][0], al, bh0 + 0);
                mma16816(acc[mt][1], ah, bh0 + 2);
                mma16816(acc[mt][1], ah, bl0 + 2);
                mma16816(acc[mt][1], al, bh0 + 2);
                mma16816(acc[mt][2], ah, bh1 + 0);
                mma16816(acc[mt][2], ah, bl1 + 0);
                mma16816(acc[mt][2], al, bh1 + 0);
                mma16816(acc[mt][3], ah, bh1 + 2);
                mma16816(acc[mt][3], ah, bl1 + 2);
                mma16816(acc[mt][3], al, bh1 + 2);
            }
        }
        __syncthreads();
    }

    // epilogue: + bias, relu, store fp32
#pragma unroll
    for (int mt = 0; mt < 2; mt++) {
        int row = m0 + wm * 32 + mt * 16 + g8;
#pragma unroll
        for (int nt = 0; nt < 4; nt++) {
            int col = n0 + wn * 32 + nt * 8 + tq * 2;
            float b0 = bias[col], b1 = bias[col + 1];
            float2 o0, o1;
            o0.x = fmaxf(acc[mt][nt][0] + b0, 0.f);
            o0.y = fmaxf(acc[mt][nt][1] + b1, 0.f);
            o1.x = fmaxf(acc[mt][nt][2] + b0, 0.f);
            o1.y = fmaxf(acc[mt][nt][3] + b1, 0.f);
            *(float2*)&O[(size_t)row * DD + col] = o0;
            *(float2*)&O[(size_t)(row + 8) * DD + col] = o1;
        }
    }
}

// ---------------- final: out = pi[0] + pi[1] ----------------
__global__ void sum_out_k(float* __restrict__ out) {
    int t0 = blockIdx.x * blockDim.x + threadIdx.x;
    int stride = gridDim.x * blockDim.x;
    const float4* p0 = (const float4*)g_pi[0];
    const float4* p1 = (const float4*)g_pi[1];
    float4* o4 = (float4*)out;
    int total = NN * CC / 4;
    for (int idx = t0; idx < total; idx += stride) {
        float4 a = p0[idx], b = p1[idx];
        o4[idx] = make_float4(a.x + b.x, a.y + b.y, a.z + b.z, a.w + b.w);
    }
}

// ---------------- launch ----------------
extern "C" void kernel_launch(void* const* d_in, const int* in_sizes, int n_in,
                              void* d_out, int out_size) {
    const float* embeddings = (const float*)d_in[0];
    const float* Wself      = (const float*)d_in[1];
    const float* Wnbr       = (const float*)d_in[2];
    const float* bvec       = (const float*)d_in[3];
    const int*   variants   = (const int*)d_in[4];
    const int*   original   = (const int*)d_in[5];
    const int*   edge_index = (const int*)d_in[6];
    float* out = (float*)d_out;
    int E = in_sizes[6] / 2;

    s1_init_k<<<512, 256>>>(embeddings, Wself, Wnbr);
    s2_prep_count_k<<<129, 256>>>(variants, original, edge_index, E);
    s3_scan_fill_k<<<1, 1024>>>(edge_index, E);

    int cur = 0;
    for (int i = 0; i < LL; i++) {
        p1_k<<<dim3(NN, VV), 192>>>(original, i, cur, i & 1);
        p2_k<<<128, 256>>>(bvec, i, cur, i & 1);
        cur ^= 1;
    }

    sum_out_k<<<1024, 256>>>(out);
}

// round 5
// speedup vs baseline: 1.4743x; 1.0062x over previous
#include <cuda_runtime.h>
#include <cuda_bf16.h>
#include <cstdint>

#define NN   2048      // nodes
#define DD   256       // embedding size
#define CC   768       // cat size
#define VV   2         // variants
#define LL   16        // activities per variant
#define EMAX 32768     // 16*N edges

// ---------------- scratch (device globals; no allocation allowed) ----------------
__device__ float g_emb[2][VV][NN * DD];     // ping-pong per variant
__device__ float g_msg[VV][NN * DD];
__device__ float g_pi[VV][NN * CC];
__device__ float g_summary[VV][2][CC];      // parity ping-pong
__device__ float g_delta[VV][2][CC];
__device__ int   g_maskedList[VV][NN];
__device__ int   g_maskedCnt[VV][2];
__device__ int   g_act[VV][LL];
__device__ int   g_later[VV][LL][LL];
__device__ int   g_laterCnt[VV][LL];
__device__ int   g_has[VV][LL];
__device__ int   g_csrCnt[NN];
__device__ int   g_csrOff[NN + 1];
__device__ int   g_csrCur[NN];
__device__ int   g_csrSrc[EMAX];
// W stacked [Wself;Wnbr] transposed: [N=256][K=512], bf16 hi/lo split
__device__ __nv_bfloat16 g_Wt_hi[DD * 2 * DD];
__device__ __nv_bfloat16 g_Wt_lo[DD * 2 * DD];

// ---------------- S1: init emb/pi/csrCnt + W convert ----------------
__global__ void s1_init_k(const float* __restrict__ embeddings,
                          const float* __restrict__ Wself, const float* __restrict__ Wnbr) {
    int t0 = blockIdx.x * blockDim.x + threadIdx.x;
    int stride = gridDim.x * blockDim.x;
    for (int idx = t0; idx < NN * DD; idx += stride) {
        float e = embeddings[idx];
        g_emb[0][0][idx] = e;
        g_emb[0][1][idx] = e;
    }
    for (int idx = t0; idx < VV * NN * CC; idx += stride) {
        ((float*)g_pi)[idx] = 0.0f;
    }
    for (int idx = t0; idx < NN; idx += stride) g_csrCnt[idx] = 0;
    for (int idx = t0; idx < DD * 2 * DD; idx += stride) {
        int n = idx >> 9;           // 0..255
        int k = idx & 511;          // 0..511
        float w = (k < DD) ? Wself[k * DD + n] : Wnbr[(k - DD) * DD + n];
        __nv_bfloat16 hi = __float2bfloat16(w);
        __nv_bfloat16 lo = __float2bfloat16(w - __bfloat162float(hi));
        g_Wt_hi[n * 512 + k] = hi;
        g_Wt_lo[n * 512 + k] = lo;
    }
}

// ---------------- S2: csr_count (blocks 0..127) + prep (block 128) ----------------
__global__ void s2_prep_count_k(const int* __restrict__ variants, const int* __restrict__ adj,
                                const int* __restrict__ ei, int E) {
    int t = threadIdx.x;                 // 256 threads
    if (blockIdx.x < 128) {
        int t0 = blockIdx.x * 256 + t;
        for (int e = t0; e < E; e += 128 * 256) atomicAdd(&g_csrCnt[ei[E + e]], 1);
        return;
    }
    // prep block
    int warp = t >> 5, lane = t & 31;
    for (int pr = warp; pr < VV * LL; pr += 8) {
        int v = pr >> 4, i = pr & 15;
        int a = variants[v * LL + i];
        if (lane == 0) {
            g_act[v][i] = a;
            int cnt = 0;
            for (int j = i + 1; j < LL; j++) {
                int nd = variants[v * LL + j];
                bool dup = false;
                for (int q = 0; q < cnt; q++) if (g_later[v][i][q] == nd) dup = true;
                if (!dup) g_later[v][i][cnt++] = nd;
            }
            g_laterCnt[v][i] = cnt;
        }
        int any = 0;
        for (int p = lane; p < NN; p += 32) any |= (adj[(size_t)a * NN + p] != 0);
        any = __any_sync(0xffffffffu, any);
        if (lane == 0) g_has[v][i] = any;
    }
    for (int idx = t; idx < VV * 2 * CC; idx += 256) {
        ((float*)g_summary)[idx] = 0.0f;
        ((float*)g_delta)[idx] = 0.0f;
    }
    if (t < VV * 2) ((int*)g_maskedCnt)[t] = 0;
}

// ---------------- S3: csr scan + fill (single block) ----------------
__global__ void s3_scan_fill_k(const int* __restrict__ ei, int E) {
    __shared__ int s[2][NN];
    int t = threadIdx.x;                 // 1024 threads
    s[0][t] = g_csrCnt[t];
    s[0][t + 1024] = g_csrCnt[t + 1024];
    __syncthreads();
    int src = 0;
    for (int off = 1; off < NN; off <<= 1) {
        int dstb = src ^ 1;
        for (int idx = t; idx < NN; idx += 1024) {
            int val = s[src][idx];
            if (idx >= off) val += s[src][idx - off];
            s[dstb][idx] = val;
        }
        __syncthreads();
        src = dstb;
    }
    for (int idx = t; idx < NN; idx += 1024) {
        int excl = (idx == 0) ? 0 : s[src][idx - 1];
        g_csrOff[idx] = excl;
        g_csrCur[idx] = excl;
    }
    if (t == 0) g_csrOff[NN] = s[src][NN - 1];
    __syncthreads();
    for (int e = t; e < E; e += 1024) {
        int dst = ei[E + e];
        int pos = atomicAdd(&g_csrCur[dst], 1);
        g_csrSrc[pos] = ei[e];
    }
}

// ---------------- P1: stepA + msg, block = p (both variants), 256 threads ----------------
__global__ __launch_bounds__(256) void p1_k(const int* __restrict__ adj, int i, int cur, int par) {
    const int p = blockIdx.x;
    const int t = threadIdx.x;
    __shared__ int s_src[192];
    __shared__ float4 sp[VV][64];

    // ---- stepA: per variant (guards are block-uniform; no smem, no syncs) ----
    for (int v = 0; v < VV; v++) {
        if (!g_has[v][i]) continue;
        const int a = g_act[v][i];
        if (adj[(size_t)a * NN + p] == 0) continue;
        const float* emb = g_emb[cur][v];
        const int cnt = g_laterCnt[v][i];

        float4 catv = make_float4(0.f, 0.f, 0.f, 0.f);
        if (t < 64)        catv = *(const float4*)&emb[(size_t)p * DD + t * 4];
        else if (t < 128)  catv = *(const float4*)&emb[(size_t)a * DD + (t - 64) * 4];

        int dest = 0;
        for (int q = 0; q < cnt; q++) {
            int lk = g_later[v][i][q];
            if (adj[(size_t)p * NN + lk] != 0) {
                dest = 1;
                if (t >= 128 && t < 192) {
                    const float4 s = *(const float4*)&emb[(size_t)lk * DD + (t - 128) * 4];
                    catv.x += s.x; catv.y += s.y; catv.z += s.z; catv.w += s.w;
                }
            }
        }
        if (!dest) continue;

        if (t < 192) {
            float* pir = &g_pi[v][(size_t)p * CC];
            float4 old = *(float4*)&pir[t * 4];
            float4 nw = make_float4(old.x + catv.x, old.y + catv.y,
                                    old.z + catv.z, old.w + catv.w);
            *(float4*)&pir[t * 4] = nw;
            float* del = g_delta[v][par];
            atomicAdd(&del[t * 4 + 0], nw.x);
            atomicAdd(&del[t * 4 + 1], nw.y);
            atomicAdd(&del[t * 4 + 2], nw.z);
            atomicAdd(&del[t * 4 + 3], nw.w);
        }
        if (t == 0) {
            int idx = atomicAdd(&g_maskedCnt[v][par], 1);
            if (idx < NN) g_maskedList[v][idx] = p;
        }
    }

    // ---- msg for dst = p, both variants in parallel ----
    // thread mapping: v = t>>7, split = (t>>6)&1, ln = t&63 (column group)
    const int mv = t >> 7;
    const int split = (t >> 6) & 1;
    const int ln = t & 63;
    const bool active = (g_has[mv][i] != 0);
    const float4* emb4 = (const float4*)g_emb[cur][mv];

    float4 acc = make_float4(0.f, 0.f, 0.f, 0.f);
    const int s0 = g_csrOff[p];
    const int deg = g_csrOff[p + 1] - s0;

    for (int base = 0; base < deg; base += 192) {
        int chunk = min(192, deg - base);
        __syncthreads();                       // protect s_src reuse across chunks
        if (t < chunk) s_src[t] = g_csrSrc[s0 + base + t];
        __syncthreads();
        if (active) {
#pragma unroll 8
            for (int j = split; j < chunk; j += 2) {
                float4 e = emb4[(size_t)s_src[j] * (DD / 4) + ln];
                acc.x += e.x; acc.y += e.y; acc.z += e.z; acc.w += e.w;
            }
        }
    }
    // reduce the two splits per variant
    if (split == 1) sp[mv][ln] = acc;          // acc==0 when inactive/deg==0: safe
    __syncthreads();
    if (split == 0 && active) {
        float4 o = sp[mv][ln];
        acc.x += o.x; acc.y += o.y; acc.z += o.z; acc.w += o.w;
        ((float4*)g_msg[mv])[(size_t)p * (DD / 4) + ln] = acc;
    }
}

// ---------------- GEMM helpers ----------------
#define SA 40
#define SB 40

__device__ __forceinline__ void mma16816(float* c, const uint32_t* a, const uint32_t* b) {
    asm volatile(
        "mma.sync.aligned.m16n8k16.row.col.f32.bf16.bf16.f32 "
        "{%0,%1,%2,%3}, {%4,%5,%6,%7}, {%8,%9}, {%0,%1,%2,%3};"
        : "+f"(c[0]), "+f"(c[1]), "+f"(c[2]), "+f"(c[3])
        : "r"(a[0]), "r"(a[1]), "r"(a[2]), "r"(a[3]), "r"(b[0]), "r"(b[1]));
}
__device__ __forceinline__ void ldsm4(uint32_t* r, uint32_t addr) {
    asm volatile("ldmatrix.sync.aligned.m8n8.x4.shared.b16 {%0,%1,%2,%3}, [%4];"
        : "=r"(r[0]), "=r"(r[1]), "=r"(r[2]), "=r"(r[3]) : "r"(addr));
}

// ---------------- P2: stepBC + GEMM, 128 blocks x 256 threads ----------------
__global__ __launch_bounds__(256) void p2_k(const float* __restrict__ bias, int i, int cur, int par) {
    const int bx = blockIdx.x;
    const int t = threadIdx.x;
    const int lane = t & 31;
    const int warp = t >> 5;

    // ---- bookkeeping: blocks 0/1 advance parity state for v=bx ----
    if (bx < VV) {
        int v = bx;
        if (t < 192) {
            float4 s = *(float4*)&g_summary[v][par][t * 4];
            float4 d = *(float4*)&g_delta[v][par][t * 4];
            s.x += d.x; s.y += d.y; s.z += d.z; s.w += d.w;
            *(float4*)&g_summary[v][par ^ 1][t * 4] = s;
            *(float4*)&g_delta[v][par ^ 1][t * 4] = make_float4(0.f, 0.f, 0.f, 0.f);
        }
        if (t == 0) g_maskedCnt[v][par ^ 1] = 0;
    }
    // ---- stepBC: pi[masked] += (summary_old + delta) ----
    for (int v = 0; v < VV; v++) {
        if (!g_has[v][i]) continue;
        int cnt = g_maskedCnt[v][par];
        if (cnt > NN) cnt = NN;
        if (cnt == 0) continue;
        float4 sd = make_float4(0.f, 0.f, 0.f, 0.f);
        if (t < 192) {
            float4 s = *(float4*)&g_summary[v][par][t * 4];
            float4 d = *(float4*)&g_delta[v][par][t * 4];
            sd = make_float4(s.x + d.x, s.y + d.y, s.z + d.z, s.w + d.w);
        }
        for (int m = bx; m < cnt; m += 128) {
            int p = g_maskedList[v][m];
            if (t < 192) {
                float* pir = &g_pi[v][(size_t)p * CC];
                float4 o = *(float4*)&pir[t * 4];
                o.x += sd.x; o.y += sd.y; o.z += sd.z; o.w += sd.w;
                *(float4*)&pir[t * 4] = o;
            }
        }
    }

    // ---- GEMM tile: bx -> (m-tile, n-tile) = (bx>>2, bx&3) ----
    const int m0g = (bx >> 2) * 128;
    const int v = m0g >> 11;
    const int m0 = m0g & 2047;
    const int n0 = (bx & 3) * 64;
    const float* X = g_emb[cur][v];
    float* O = g_emb[cur ^ 1][v];

    if (!g_has[v][i]) {
        int r = t >> 1, ch = (t & 1) * 32;
#pragma unroll
        for (int j = 0; j < 8; j++) {
            *(float4*)&O[(size_t)(m0 + r) * DD + n0 + ch + j * 4] =
                *(const float4*)&X[(size_t)(m0 + r) * DD + n0 + ch + j * 4];
        }
        return;
    }

    const float* Msg = g_msg[v];
    __shared__ __align__(16) __nv_bfloat16 As[2][128][SA];   // [hi/lo]
    __shared__ __align__(16) __nv_bfloat16 Bs[2][64][SB];

    const int wm = warp >> 1;            // 0..3
    const int wn = warp & 1;             // 0..1
    const int g8 = lane >> 2;
    const int tq = lane & 3;

    float acc[2][4][4];
#pragma unroll
    for (int mt = 0; mt < 2; mt++)
#pragma unroll
        for (int nt = 0; nt < 4; nt++)
#pragma unroll
            for (int e = 0; e < 4; e++) acc[mt][nt][e] = 0.f;

    // precompute ldmatrix lane addresses (tile smem reused every kt)
    uint32_t aaddr[2][2], baddr[2][2];   // [mt|q][h]
    {
        int arow = wm * 32 + (lane & 15);
        int acol = (lane >> 4) * 8;
        aaddr[0][0] = (uint32_t)__cvta_generic_to_shared(&As[0][arow][acol]);
        aaddr[1][0] = (uint32_t)__cvta_generic_to_shared(&As[0][arow + 16][acol]);
        aaddr[0][1] = (uint32_t)__cvta_generic_to_shared(&As[1][arow][acol]);
        aaddr[1][1] = (uint32_t)__cvta_generic_to_shared(&As[1][arow + 16][acol]);
        int brow = wn * 32 + (lane & 7) + ((lane >> 4) << 3);
        int bcol = ((lane >> 3) & 1) * 8;
        baddr[0][0] = (uint32_t)__cvta_generic_to_shared(&Bs[0][brow][bcol]);
        baddr[1][0] = (uint32_t)__cvta_generic_to_shared(&Bs[0][brow + 16][bcol]);
        baddr[0][1] = (uint32_t)__cvta_generic_to_shared(&Bs[1][brow][bcol]);
        baddr[1][1] = (uint32_t)__cvta_generic_to_shared(&Bs[1][brow + 16][bcol]);
    }

    const int aq = t & 7;
    const int ar0 = t >> 3;
    const int bn = t >> 2;
    const int bseg = t & 3;

    for (int kt = 0; kt < 512; kt += 32) {
        const float* Asrc = (kt < 256) ? X : Msg;
        int colbase = (kt & 255) + aq * 4;
#pragma unroll
        for (int rr = 0; rr < 4; rr++) {
            int row = ar0 + rr * 32;
            float4 f = *(const float4*)&Asrc[(size_t)(m0 + row) * DD + colbase];
            __nv_bfloat162 h0 = __floats2bfloat162_rn(f.x, f.y);
            __nv_bfloat162 h1 = __floats2bfloat162_rn(f.z, f.w);
            __nv_bfloat162 l0 = __floats2bfloat162_rn(f.x - __bfloat162float(h0.x),
                                                      f.y - __bfloat162float(h0.y));
            __nv_bfloat162 l1 = __floats2bfloat162_rn(f.z - __bfloat162float(h1.x),
                                                      f.w - __bfloat162float(h1.y));
            *(__nv_bfloat162*)&As[0][row][aq * 4]     = h0;
            *(__nv_bfloat162*)&As[0][row][aq * 4 + 2] = h1;
            *(__nv_bfloat162*)&As[1][row][aq * 4]     = l0;
            *(__nv_bfloat162*)&As[1][row][aq * 4 + 2] = l1;
        }
        {
            size_t woff = (size_t)(n0 + bn) * 512 + kt + bseg * 8;
            *(uint4*)&Bs[0][bn][bseg * 8] = *(const uint4*)&g_Wt_hi[woff];
            *(uint4*)&Bs[1][bn][bseg * 8] = *(const uint4*)&g_Wt_lo[woff];
        }
        __syncthreads();

#pragma unroll
        for (int sub = 0; sub < 2; sub++) {
            uint32_t off = sub * 32;     // 16 bf16 = 32 bytes
            uint32_t ah0[4], ah1[4], al0[4], al1[4];
            uint32_t bh0[4], bh1[4], bl0[4], bl1[4];
            ldsm4(ah0, aaddr[0][0] + off);
            ldsm4(ah1, aaddr[1][0] + off);
            ldsm4(al0, aaddr[0][1] + off);
            ldsm4(al1, aaddr[1][1] + off);
            ldsm4(bh0, baddr[0][0] + off);
            ldsm4(bh1, baddr[1][0] + off);
            ldsm4(bl0, baddr[0][1] + off);
            ldsm4(bl1, baddr[1][1] + off);
#pragma unroll
            for (int mt = 0; mt < 2; mt++) {
                const uint32_t* ah = mt ? ah1 : ah0;
                const uint32_t* al = mt ? al1 : al0;
                mma16816(acc[mt][0], ah, bh0 + 0);
                mma16816(acc[mt][0], ah, bl0 + 0);
                mma16816(acc[mt][0], al, bh0 + 0);
                mma16816(acc[mt][1], ah, bh0 + 2);
                mma16816(acc[mt][1], ah, bl0 + 2);
                mma16816(acc[mt][1], al, bh0 + 2);
                mma16816(acc[mt][2], ah, bh1 + 0);
                mma16816(acc[mt][2], ah, bl1 + 0);
                mma16816(acc[mt][2], al, bh1 + 0);
                mma16816(acc[mt][3], ah, bh1 + 2);
                mma16816(acc[mt][3], ah, bl1 + 2);
                mma16816(acc[mt][3], al, bh1 + 2);
            }
        }
        __syncthreads();
    }

    // epilogue: + bias, relu, store fp32
#pragma unroll
    for (int mt = 0; mt < 2; mt++) {
        int row = m0 + wm * 32 + mt * 16 + g8;
#pragma unroll
        for (int nt = 0; nt < 4; nt++) {
            int col = n0 + wn * 32 + nt * 8 + tq * 2;
            float b0 = bias[col], b1 = bias[col + 1];
            float2 o0, o1;
            o0.x = fmaxf(acc[mt][nt][0] + b0, 0.f);
            o0.y = fmaxf(acc[mt][nt][1] + b1, 0.f);
            o1.x = fmaxf(acc[mt][nt][2] + b0, 0.f);
            o1.y = fmaxf(acc[mt][nt][3] + b1, 0.f);
            *(float2*)&O[(size_t)row * DD + col] = o0;
            *(float2*)&O[(size_t)(row + 8) * DD + col] = o1;
        }
    }
}

// ---------------- final: out = pi[0] + pi[1] ----------------
__global__ void sum_out_k(float* __restrict__ out) {
    int t0 = blockIdx.x * blockDim.x + threadIdx.x;
    int stride = gridDim.x * blockDim.x;
    const float4* p0 = (const float4*)g_pi[0];
    const float4* p1 = (const float4*)g_pi[1];
    float4* o4 = (float4*)out;
    int total = NN * CC / 4;
    for (int idx = t0; idx < total; idx += stride) {
        float4 a = p0[idx], b = p1[idx];
        o4[idx] = make_float4(a.x + b.x, a.y + b.y, a.z + b.z, a.w + b.w);
    }
}

// ---------------- launch ----------------
extern "C" void kernel_launch(void* const* d_in, const int* in_sizes, int n_in,
                              void* d_out, int out_size) {
    const float* embeddings = (const float*)d_in[0];
    const float* Wself      = (const float*)d_in[1];
    const float* Wnbr       = (const float*)d_in[2];
    const float* bvec       = (const float*)d_in[3];
    const int*   variants   = (const int*)d_in[4];
    const int*   original   = (const int*)d_in[5];
    const int*   edge_index = (const int*)d_in[6];
    float* out = (float*)d_out;
    int E = in_sizes[6] / 2;

    s1_init_k<<<512, 256>>>(embeddings, Wself, Wnbr);
    s2_prep_count_k<<<129, 256>>>(variants, original, edge_index, E);
    s3_scan_fill_k<<<1, 1024>>>(edge_index, E);

    int cur = 0;
    for (int i = 0; i < LL; i++) {
        p1_k<<<NN, 256>>>(original, i, cur, i & 1);
        p2_k<<<128, 256>>>(bvec, i, cur, i & 1);
        cur ^= 1;
    }

    sum_out_k<<<1024, 256>>>(out);
}

// round 6
// speedup vs baseline: 1.5919x; 1.0798x over previous
#include <cuda_runtime.h>
#include <cuda_bf16.h>
#include <cstdint>

#define NN   2048      // nodes
#define DD   256       // embedding size
#define CC   768       // cat size
#define VV   2         // variants
#define LL   16        // activities per variant
#define EMAX 32768     // 16*N edges
#define MAXCAND 256

// ---------------- scratch (device globals; no allocation allowed) ----------------
__device__ float g_emb[2][VV][NN * DD];     // ping-pong per variant
__device__ float g_msg[VV][NN * DD];
__device__ float g_pi[VV][NN * CC];
__device__ float g_summary[VV][CC];         // persistent across steps
__device__ int   g_act[VV][LL];
__device__ int   g_later[VV][LL][LL];
__device__ int   g_laterCnt[VV][LL];
__device__ int   g_has[VV][LL];
__device__ int   g_csrCnt[NN];
__device__ int   g_csrOff[NN + 1];
__device__ int   g_csrCur[NN];
__device__ int   g_csrSrc[EMAX];
// W stacked [Wself;Wnbr] transposed: [N=256][K=512], bf16 hi/lo split
__device__ __nv_bfloat16 g_Wt_hi[DD * 2 * DD];
__device__ __nv_bfloat16 g_Wt_lo[DD * 2 * DD];

// ---------------- S1: init emb/pi/csrCnt + W convert ----------------
__global__ void s1_init_k(const float* __restrict__ embeddings,
                          const float* __restrict__ Wself, const float* __restrict__ Wnbr) {
    int t0 = blockIdx.x * blockDim.x + threadIdx.x;
    int stride = gridDim.x * blockDim.x;
    for (int idx = t0; idx < NN * DD; idx += stride) {
        float e = embeddings[idx];
        g_emb[0][0][idx] = e;
        g_emb[0][1][idx] = e;
    }
    for (int idx = t0; idx < VV * NN * CC; idx += stride) {
        ((float*)g_pi)[idx] = 0.0f;
    }
    for (int idx = t0; idx < NN; idx += stride) g_csrCnt[idx] = 0;
    for (int idx = t0; idx < DD * 2 * DD; idx += stride) {
        int n = idx >> 9;           // 0..255
        int k = idx & 511;          // 0..511
        float w = (k < DD) ? Wself[k * DD + n] : Wnbr[(k - DD) * DD + n];
        __nv_bfloat16 hi = __float2bfloat16(w);
        __nv_bfloat16 lo = __float2bfloat16(w - __bfloat162float(hi));
        g_Wt_hi[n * 512 + k] = hi;
        g_Wt_lo[n * 512 + k] = lo;
    }
}

// ---------------- S2: csr_count (blocks 0..127) + prep (block 128) ----------------
__global__ void s2_prep_count_k(const int* __restrict__ variants, const int* __restrict__ adj,
                                const int* __restrict__ ei, int E) {
    int t = threadIdx.x;                 // 256 threads
    if (blockIdx.x < 128) {
        int t0 = blockIdx.x * 256 + t;
        for (int e = t0; e < E; e += 128 * 256) atomicAdd(&g_csrCnt[ei[E + e]], 1);
        return;
    }
    // prep block
    int warp = t >> 5, lane = t & 31;
    for (int pr = warp; pr < VV * LL; pr += 8) {
        int v = pr >> 4, i = pr & 15;
        int a = variants[v * LL + i];
        if (lane == 0) {
            g_act[v][i] = a;
            int cnt = 0;
            for (int j = i + 1; j < LL; j++) {
                int nd = variants[v * LL + j];
                bool dup = false;
                for (int q = 0; q < cnt; q++) if (g_later[v][i][q] == nd) dup = true;
                if (!dup) g_later[v][i][cnt++] = nd;
            }
            g_laterCnt[v][i] = cnt;
        }
        int any = 0;
        for (int p = lane; p < NN; p += 32) any |= (adj[(size_t)a * NN + p] != 0);
        any = __any_sync(0xffffffffu, any);
        if (lane == 0) g_has[v][i] = any;
    }
    for (int idx = t; idx < VV * CC; idx += 256) {
        ((float*)g_summary)[idx] = 0.0f;
    }
}

// ---------------- S3: csr scan + fill (single block) ----------------
__global__ void s3_scan_fill_k(const int* __restrict__ ei, int E) {
    __shared__ int s[2][NN];
    int t = threadIdx.x;                 // 1024 threads
    s[0][t] = g_csrCnt[t];
    s[0][t + 1024] = g_csrCnt[t + 1024];
    __syncthreads();
    int src = 0;
    for (int off = 1; off < NN; off <<= 1) {
        int dstb = src ^ 1;
        for (int idx = t; idx < NN; idx += 1024) {
            int val = s[src][idx];
            if (idx >= off) val += s[src][idx - off];
            s[dstb][idx] = val;
        }
        __syncthreads();
        src = dstb;
    }
    for (int idx = t; idx < NN; idx += 1024) {
        int excl = (idx == 0) ? 0 : s[src][idx - 1];
        g_csrOff[idx] = excl;
        g_csrCur[idx] = excl;
    }
    if (t == 0) g_csrOff[NN] = s[src][NN - 1];
    __syncthreads();
    for (int e = t; e < E; e += 1024) {
        int dst = ei[E + e];
        int pos = atomicAdd(&g_csrCur[dst], 1);
        g_csrSrc[pos] = ei[e];
    }
}

// ---------------- Q: pure msg gather, block = (dst, v), 64 threads ----------------
__global__ __launch_bounds__(64) void q_msg_k(int i, int cur) {
    const int p = blockIdx.x, v = blockIdx.y;
    if (!g_has[v][i]) return;
    const float4* __restrict__ emb4 = (const float4*)g_emb[cur][v];
    const int t = threadIdx.x;           // 64 threads x float4 = 256 cols
    float4 acc = make_float4(0.f, 0.f, 0.f, 0.f);
    const int s0 = g_csrOff[p], s1 = g_csrOff[p + 1];
#pragma unroll 4
    for (int j = s0; j < s1; j++) {
        int s = __ldg(&g_csrSrc[j]);
        float4 e = __ldg(&emb4[(size_t)s * (DD / 4) + t]);
        acc.x += e.x; acc.y += e.y; acc.z += e.z; acc.w += e.w;
    }
    ((float4*)g_msg[v])[(size_t)p * (DD / 4) + t] = acc;
}

// ---------------- GEMM helpers ----------------
#define SA 40
#define SB 40

__device__ __forceinline__ void mma16816(float* c, const uint32_t* a, const uint32_t* b) {
    asm volatile(
        "mma.sync.aligned.m16n8k16.row.col.f32.bf16.bf16.f32 "
        "{%0,%1,%2,%3}, {%4,%5,%6,%7}, {%8,%9}, {%0,%1,%2,%3};"
        : "+f"(c[0]), "+f"(c[1]), "+f"(c[2]), "+f"(c[3])
        : "r"(a[0]), "r"(a[1]), "r"(a[2]), "r"(a[3]), "r"(b[0]), "r"(b[1]));
}
__device__ __forceinline__ void ldsm4(uint32_t* r, uint32_t addr) {
    asm volatile("ldmatrix.sync.aligned.m8n8.x4.shared.b16 {%0,%1,%2,%3}, [%4];"
        : "=r"(r[0]), "=r"(r[1]), "=r"(r[2]), "=r"(r[3]) : "r"(addr));
}

// ---------------- R: GEMM (blocks 0..127) + stepA/BC (block 128), 256 threads ----------------
__global__ __launch_bounds__(256) void r_k(const int* __restrict__ adj,
                                           const float* __restrict__ bias, int i, int cur) {
    const int bx = blockIdx.x;
    const int t = threadIdx.x;
    const int lane = t & 31;
    const int warp = t >> 5;

    __shared__ __align__(16) __nv_bfloat16 As[2][128][SA];   // [hi/lo]
    __shared__ __align__(16) __nv_bfloat16 Bs[2][64][SB];
    __shared__ float s_delta[VV][CC];
    __shared__ int s_cand[VV][MAXCAND];
    __shared__ unsigned s_dmask[VV][MAXCAND];
    __shared__ int s_ncand[VV];

    if (bx == 128) {
        // ============ stepA + stepBC, whole step, one block ============
        // Phase 0: zero delta, counters
        for (int idx = t; idx < VV * CC; idx += 256) ((float*)s_delta)[idx] = 0.f;
        if (t < VV) s_ncand[t] = 0;
        __syncthreads();

        // Phase A: candidate scan (followers of a)
        for (int v = 0; v < VV; v++) {
            if (!g_has[v][i]) continue;
            const int a = g_act[v][i];
            for (int p = t; p < NN; p += 256) {
                if (adj[(size_t)a * NN + p] != 0) {
                    int id = atomicAdd(&s_ncand[v], 1);
                    if (id < MAXCAND) s_cand[v][id] = p;
                }
            }
        }
        __syncthreads();

        // Phase B: dest-set probe, warp per candidate
        for (int v = 0; v < VV; v++) {
            if (!g_has[v][i]) continue;
            int nc = min(s_ncand[v], MAXCAND);
            const int cnt = g_laterCnt[v][i];
            for (int c = warp; c < nc; c += 8) {
                int p = s_cand[v][c];
                int hit = (lane < cnt) ? (adj[(size_t)p * NN + g_later[v][i][lane]] != 0) : 0;
                unsigned dm = __ballot_sync(0xffffffffu, hit);
                if (lane == 0) s_dmask[v][c] = dm;
            }
        }
        __syncthreads();

        // Phase C: pi[p] += cat; delta += pi_new  (warp per masked candidate)
        for (int v = 0; v < VV; v++) {
            if (!g_has[v][i]) continue;
            int nc = min(s_ncand[v], MAXCAND);
            const int a = g_act[v][i];
            const float* emb = g_emb[cur][v];
            for (int c = warp; c < nc; c += 8) {
                unsigned dm = s_dmask[v][c];
                if (!dm) continue;
                int p = s_cand[v][c];
#pragma unroll
                for (int ch = 0; ch < 6; ch++) {
                    int col = ch * 128 + lane * 4;       // 0..764
                    float4 cat;
                    if (col < 256) {
                        cat = *(const float4*)&emb[(size_t)p * DD + col];
                    } else if (col < 512) {
                        cat = *(const float4*)&emb[(size_t)a * DD + (col - 256)];
                    } else {
                        cat = make_float4(0.f, 0.f, 0.f, 0.f);
                        unsigned m = dm;
                        while (m) {
                            int q = __ffs(m) - 1; m &= m - 1;
                            int lk = g_later[v][i][q];
                            float4 e = *(const float4*)&emb[(size_t)lk * DD + (col - 512)];
                            cat.x += e.x; cat.y += e.y; cat.z += e.z; cat.w += e.w;
                        }
                    }
                    float* pir = &g_pi[v][(size_t)p * CC + col];
                    float4 pn = *(float4*)pir;
                    pn.x += cat.x; pn.y += cat.y; pn.z += cat.z; pn.w += cat.w;
                    *(float4*)pir = pn;
                    atomicAdd(&s_delta[v][col + 0], pn.x);
                    atomicAdd(&s_delta[v][col + 1], pn.y);
                    atomicAdd(&s_delta[v][col + 2], pn.z);
                    atomicAdd(&s_delta[v][col + 3], pn.w);
                }
            }
        }
        __syncthreads();

        // Phase D: summary_new = summary_old + delta; persist; reuse s_delta as summary_new
        for (int v = 0; v < VV; v++) {
            if (!g_has[v][i]) continue;
            if (t < 192) {
                float4 s = *(float4*)&g_summary[v][t * 4];
                float4 d = *(float4*)&s_delta[v][t * 4];
                s.x += d.x; s.y += d.y; s.z += d.z; s.w += d.w;
                *(float4*)&g_summary[v][t * 4] = s;
                *(float4*)&s_delta[v][t * 4] = s;
            }
        }
        __syncthreads();

        // Phase E: pi[masked] += summary_new  (warp per masked candidate)
        for (int v = 0; v < VV; v++) {
            if (!g_has[v][i]) continue;
            int nc = min(s_ncand[v], MAXCAND);
            for (int c = warp; c < nc; c += 8) {
                if (!s_dmask[v][c]) continue;
                int p = s_cand[v][c];
#pragma unroll
                for (int ch = 0; ch < 6; ch++) {
                    int col = ch * 128 + lane * 4;
                    float4 s = *(float4*)&s_delta[v][col];
                    float* pir = &g_pi[v][(size_t)p * CC + col];
                    float4 o = *(float4*)pir;
                    o.x += s.x; o.y += s.y; o.z += s.z; o.w += s.w;
                    *(float4*)pir = o;
                }
            }
        }
        return;
    }

    // ============ GEMM tile: bx -> (m-tile, n-tile) = (bx>>2, bx&3) ============
    const int m0g = (bx >> 2) * 128;
    const int v = m0g >> 11;
    const int m0 = m0g & 2047;
    const int n0 = (bx & 3) * 64;
    const float* X = g_emb[cur][v];
    float* O = g_emb[cur ^ 1][v];

    if (!g_has[v][i]) {
        int r = t >> 1, ch = (t & 1) * 32;
#pragma unroll
        for (int j = 0; j < 8; j++) {
            *(float4*)&O[(size_t)(m0 + r) * DD + n0 + ch + j * 4] =
                *(const float4*)&X[(size_t)(m0 + r) * DD + n0 + ch + j * 4];
        }
        return;
    }

    const float* Msg = g_msg[v];
    const int wm = warp >> 1;            // 0..3
    const int wn = warp & 1;             // 0..1
    const int g8 = lane >> 2;
    const int tq = lane & 3;

    float acc[2][4][4];
#pragma unroll
    for (int mt = 0; mt < 2; mt++)
#pragma unroll
        for (int nt = 0; nt < 4; nt++)
#pragma unroll
            for (int e = 0; e < 4; e++) acc[mt][nt][e] = 0.f;

    // precompute ldmatrix lane addresses
    uint32_t aaddr[2][2], baddr[2][2];   // [mt|q][h]
    {
        int arow = wm * 32 + (lane & 15);
        int acol = (lane >> 4) * 8;
        aaddr[0][0] = (uint32_t)__cvta_generic_to_shared(&As[0][arow][acol]);
        aaddr[1][0] = (uint32_t)__cvta_generic_to_shared(&As[0][arow + 16][acol]);
        aaddr[0][1] = (uint32_t)__cvta_generic_to_shared(&As[1][arow][acol]);
        aaddr[1][1] = (uint32_t)__cvta_generic_to_shared(&As[1][arow + 16][acol]);
        int brow = wn * 32 + (lane & 7) + ((lane >> 4) << 3);
        int bcol = ((lane >> 3) & 1) * 8;
        baddr[0][0] = (uint32_t)__cvta_generic_to_shared(&Bs[0][brow][bcol]);
        baddr[1][0] = (uint32_t)__cvta_generic_to_shared(&Bs[0][brow + 16][bcol]);
        baddr[0][1] = (uint32_t)__cvta_generic_to_shared(&Bs[1][brow][bcol]);
        baddr[1][1] = (uint32_t)__cvta_generic_to_shared(&Bs[1][brow + 16][bcol]);
    }

    const int aq = t & 7;
    const int ar0 = t >> 3;
    const int bn = t >> 2;
    const int bseg = t & 3;

    for (int kt = 0; kt < 512; kt += 32) {
        const float* Asrc = (kt < 256) ? X : Msg;
        int colbase = (kt & 255) + aq * 4;
#pragma unroll
        for (int rr = 0; rr < 4; rr++) {
            int row = ar0 + rr * 32;
            float4 f = *(const float4*)&Asrc[(size_t)(m0 + row) * DD + colbase];
            __nv_bfloat162 h0 = __floats2bfloat162_rn(f.x, f.y);
            __nv_bfloat162 h1 = __floats2bfloat162_rn(f.z, f.w);
            __nv_bfloat162 l0 = __floats2bfloat162_rn(f.x - __bfloat162float(h0.x),
                                                      f.y - __bfloat162float(h0.y));
            __nv_bfloat162 l1 = __floats2bfloat162_rn(f.z - __bfloat162float(h1.x),
                                                      f.w - __bfloat162float(h1.y));
            *(__nv_bfloat162*)&As[0][row][aq * 4]     = h0;
            *(__nv_bfloat162*)&As[0][row][aq * 4 + 2] = h1;
            *(__nv_bfloat162*)&As[1][row][aq * 4]     = l0;
            *(__nv_bfloat162*)&As[1][row][aq * 4 + 2] = l1;
        }
        {
            size_t woff = (size_t)(n0 + bn) * 512 + kt + bseg * 8;
            *(uint4*)&Bs[0][bn][bseg * 8] = *(const uint4*)&g_Wt_hi[woff];
            *(uint4*)&Bs[1][bn][bseg * 8] = *(const uint4*)&g_Wt_lo[woff];
        }
        __syncthreads();

#pragma unroll
        for (int sub = 0; sub < 2; sub++) {
            uint32_t off = sub * 32;     // 16 bf16 = 32 bytes
            uint32_t ah0[4], ah1[4], al0[4], al1[4];
            uint32_t bh0[4], bh1[4], bl0[4], bl1[4];
            ldsm4(ah0, aaddr[0][0] + off);
            ldsm4(ah1, aaddr[1][0] + off);
            ldsm4(al0, aaddr[0][1] + off);
            ldsm4(al1, aaddr[1][1] + off);
            ldsm4(bh0, baddr[0][0] + off);
            ldsm4(bh1, baddr[1][0] + off);
            ldsm4(bl0, baddr[0][1] + off);
            ldsm4(bl1, baddr[1][1] + off);
#pragma unroll
            for (int mt = 0; mt < 2; mt++) {
                const uint32_t* ah = mt ? ah1 : ah0;
                const uint32_t* al = mt ? al1 : al0;
                mma16816(acc[mt][0], ah, bh0 + 0);
                mma16816(acc[mt][0], ah, bl0 + 0);
                mma16816(acc[mt][0], al, bh0 + 0);
                mma16816(acc[mt][1], ah, bh0 + 2);
                mma16816(acc[mt][1], ah, bl0 + 2);
                mma16816(acc[mt][1], al, bh0 + 2);
                mma16816(acc[mt][2], ah, bh1 + 0);
                mma16816(acc[mt][2], ah, bl1 + 0);
                mma16816(acc[mt][2], al, bh1 + 0);
                mma16816(acc[mt][3], ah, bh1 + 2);
                mma16816(acc[mt][3], ah, bl1 + 2);
                mma16816(acc[mt][3], al, bh1 + 2);
            }
        }
        __syncthreads();
    }

    // epilogue: + bias, relu, store fp32
#pragma unroll
    for (int mt = 0; mt < 2; mt++) {
        int row = m0 + wm * 32 + mt * 16 + g8;
#pragma unroll
        for (int nt = 0; nt < 4; nt++) {
            int col = n0 + wn * 32 + nt * 8 + tq * 2;
            float b0 = bias[col], b1 = bias[col + 1];
            float2 o0, o1;
            o0.x = fmaxf(acc[mt][nt][0] + b0, 0.f);
            o0.y = fmaxf(acc[mt][nt][1] + b1, 0.f);
            o1.x = fmaxf(acc[mt][nt][2] + b0, 0.f);
            o1.y = fmaxf(acc[mt][nt][3] + b1, 0.f);
            *(float2*)&O[(size_t)row * DD + col] = o0;
            *(float2*)&O[(size_t)(row + 8) * DD + col] = o1;
        }
    }
}

// ---------------- final: out = pi[0] + pi[1] ----------------
__global__ void sum_out_k(float* __restrict__ out) {
    int t0 = blockIdx.x * blockDim.x + threadIdx.x;
    int stride = gridDim.x * blockDim.x;
    const float4* p0 = (const float4*)g_pi[0];
    const float4* p1 = (const float4*)g_pi[1];
    float4* o4 = (float4*)out;
    int total = NN * CC / 4;
    for (int idx = t0; idx < total; idx += stride) {
        float4 a = p0[idx], b = p1[idx];
        o4[idx] = make_float4(a.x + b.x, a.y + b.y, a.z + b.z, a.w + b.w);
    }
}

// ---------------- launch ----------------
extern "C" void kernel_launch(void* const* d_in, const int* in_sizes, int n_in,
                              void* d_out, int out_size) {
    const float* embeddings = (const float*)d_in[0];
    const float* Wself      = (const float*)d_in[1];
    const float* Wnbr       = (const float*)d_in[2];
    const float* bvec       = (const float*)d_in[3];
    const int*   variants   = (const int*)d_in[4];
    const int*   original   = (const int*)d_in[5];
    const int*   edge_index = (const int*)d_in[6];
    float* out = (float*)d_out;
    int E = in_sizes[6] / 2;

    s1_init_k<<<512, 256>>>(embeddings, Wself, Wnbr);
    s2_prep_count_k<<<129, 256>>>(variants, original, edge_index, E);
    s3_scan_fill_k<<<1, 1024>>>(edge_index, E);

    int cur = 0;
    for (int i = 0; i < LL; i++) {
        q_msg_k<<<dim3(NN, VV), 64>>>(i, cur);
        r_k<<<129, 256>>>(original, bvec, i, cur);
        cur ^= 1;
    }

    sum_out_k<<<1024, 256>>>(out);
}